// round 15
// baseline (speedup 1.0000x reference)
#include <cuda_runtime.h>
#include <math.h>
#include <stdint.h>

#define Bn 4
#define Tn 1024
#define Sn 64
#define En 128
#define NHn 4
#define DHn 32
#define FFn 256
#define Ln 3
#define Cn 4
#define SX 132            // row-major stride; 132 mod 32 = 4 -> conflict-free A-frags
#define SF 260            // FF stride; 260 mod 32 = 4
#define NTHREADS 512

// packed weights: per layer {wq,wk,wv,wo: 8192 each, w1: 16384, w2: 16384} = 65536 float2
#define LSTRIDE 65536
__device__ float2 g_wpacked[3*LSTRIDE];

#define BAR_GROUP(id) asm volatile("bar.sync %0, 128;" :: "r"(id) : "memory")

// ---- tf32 helpers ----
__device__ __forceinline__ uint32_t totf(float f){
    uint32_t u; asm("cvt.rna.tf32.f32 %0, %1;" : "=r"(u) : "f"(f)); return u;
}
__device__ __forceinline__ float rtf(float f){ return __uint_as_float(totf(f)); }
__device__ __forceinline__ void mma_tf32(float d[4], const uint32_t a[4], const uint32_t b[2]){
    asm("mma.sync.aligned.m16n8k8.row.col.f32.tf32.tf32.f32 "
        "{%0,%1,%2,%3},{%4,%5,%6,%7},{%8,%9},{%0,%1,%2,%3};"
        : "+f"(d[0]), "+f"(d[1]), "+f"(d[2]), "+f"(d[3])
        : "r"(a[0]), "r"(a[1]), "r"(a[2]), "r"(a[3]), "r"(b[0]), "r"(b[1]));
}

__device__ __forceinline__ float gelu_tanh(float x){
    float x3 = x*x*x;
    float t = tanhf(0.7978845608028654f*(x + 0.044715f*x3));
    return 0.5f*x*(1.0f + t);
}

// ---- weight prep: tf32-round + fragment-pack ----
__global__ void prep_weights(const float* __restrict__ wq, const float* __restrict__ wk,
                             const float* __restrict__ wv, const float* __restrict__ wo,
                             const float* __restrict__ w1, const float* __restrict__ w2)
{
    const int y = blockIdx.y;
    const int l = y / 6, w = y - 6*l;
    const float* W; int IC, OC; int off;
    switch (w){
        case 0: W = wq + l*En*En;  IC = En;  OC = En;  off = 0;     break;
        case 1: W = wk + l*En*En;  IC = En;  OC = En;  off = 8192;  break;
        case 2: W = wv + l*En*En;  IC = En;  OC = En;  off = 16384; break;
        case 3: W = wo + l*En*En;  IC = En;  OC = En;  off = 24576; break;
        case 4: W = w1 + l*En*FFn; IC = En;  OC = FFn; off = 32768; break;
        default:W = w2 + l*FFn*En; IC = FFn; OC = En;  off = 49152; break;
    }
    const int total = (IC >> 3) * OC * 4;
    float2* dst = g_wpacked + l*LSTRIDE + off;
    for (int idx = blockIdx.x*blockDim.x + threadIdx.x; idx < total;
         idx += gridDim.x*blockDim.x){
        const int tig = idx & 3;
        const int rem = idx >> 2;
        const int n   = rem % OC;
        const int ks  = rem / OC;
        const float a = W[(ks*8 + tig)*OC + n];
        const float b = W[(ks*8 + tig + 4)*OC + n];
        dst[idx] = make_float2(__uint_as_float(totf(a)), __uint_as_float(totf(b)));
    }
}

// ---- warp-local layernorm: warp normalizes rows m0..m0+15 (2 lanes/row) ----
// Dead rows (>= valid) written as zero. Full-mask shuffles (warp uniform).
__device__ __forceinline__ void ln_warp(const float* __restrict__ src,
        float* __restrict__ dst, const float* __restrict__ g,
        const float* __restrict__ b, int m0, int valid)
{
    const int lane = threadIdx.x & 31;
    const int p = lane >> 1, e = lane & 1;
    const int row = m0 + p;
    const float* xr = src + row*SX;
    float s = 0.f, s2 = 0.f;
    #pragma unroll
    for (int i = 0; i < 64; i++){
        float v = xr[e + 2*i];
        s += v; s2 = fmaf(v, v, s2);
    }
    s  += __shfl_xor_sync(0xffffffffu, s, 1);
    s2 += __shfl_xor_sync(0xffffffffu, s2, 1);
    const float m    = s * 0.0078125f;
    const float rstd = rsqrtf(s2*0.0078125f - m*m + 1e-5f);
    const bool live  = row < valid;
    float* dr = dst + row*SX;
    #pragma unroll
    for (int i = 0; i < 64; i++){
        int c = e + 2*i;
        dr[c] = live ? rtf((xr[c] - m)*rstd*g[c] + b[c]) : 0.f;
    }
}

// ---- GEMM 16x32 tile into REGISTERS (Q path): RoPE + rtf applied, no store ----
template<int IC, int OC, int SS>
__device__ __forceinline__ void mma_tile_regs(const float* __restrict__ src,
        const float2* __restrict__ Wp, const float* __restrict__ bias,
        int m0, int n0, const float* __restrict__ RCp, const float* __restrict__ RSp,
        float d[4][4])
{
    const int lane = threadIdx.x & 31;
    const int g    = lane >> 2;
    const int tig  = lane & 3;
    const int NK   = IC / 8;

    #pragma unroll
    for (int nt = 0; nt < 4; nt++){
        const float2 bb = *(const float2*)(bias + n0 + nt*8 + 2*tig);
        d[nt][0] = bb.x; d[nt][1] = bb.y; d[nt][2] = bb.x; d[nt][3] = bb.y;
    }
    const float* s0 = src + (m0 + g)*SS + tig;
    const float* s1 = src + (m0 + g + 8)*SS + tig;
    const float2* Wb = Wp + (size_t)(n0 + g)*4 + tig;

    float aC[4]; float2 bC[4];
    aC[0] = s0[0]; aC[1] = s1[0]; aC[2] = s0[4]; aC[3] = s1[4];
    #pragma unroll
    for (int nt = 0; nt < 4; nt++) bC[nt] = __ldg(Wb + nt*32);

    #pragma unroll 1
    for (int ks = 0; ks < NK; ks++){
        const int k1 = (ks + 1 < NK) ? (ks + 1)*8 : ks*8;
        const float2* Wn = Wb + (size_t)((ks + 1 < NK) ? (ks + 1) : ks)*OC*4;
        float aN[4]; float2 bN[4];
        aN[0] = s0[k1]; aN[1] = s1[k1]; aN[2] = s0[k1+4]; aN[3] = s1[k1+4];
        #pragma unroll
        for (int nt = 0; nt < 4; nt++) bN[nt] = __ldg(Wn + nt*32);
        uint32_t ua[4];
        #pragma unroll
        for (int i = 0; i < 4; i++) ua[i] = __float_as_uint(aC[i]);
        #pragma unroll
        for (int nt = 0; nt < 4; nt++){
            uint32_t ub[2] = { __float_as_uint(bC[nt].x), __float_as_uint(bC[nt].y) };
            mma_tf32(d[nt], ua, ub);
        }
        #pragma unroll
        for (int i = 0; i < 4; i++) aC[i] = aN[i];
        #pragma unroll
        for (int nt = 0; nt < 4; nt++) bC[nt] = bN[nt];
    }
    // RoPE (n-chunk == one head) + tf32 rounding, all in registers
    #pragma unroll
    for (int nt = 0; nt < 2; nt++){
        const int j = nt*8 + 2*tig;
        const float2 c0 = *(const float2*)(RCp + (m0 + g)*16 + j);
        const float2 s0v= *(const float2*)(RSp + (m0 + g)*16 + j);
        const float2 c1 = *(const float2*)(RCp + (m0 + g + 8)*16 + j);
        const float2 s1v= *(const float2*)(RSp + (m0 + g + 8)*16 + j);
        float t1, t2;
        t1 = d[nt][0]; t2 = d[nt+2][0];
        d[nt][0] = t1*c0.x - t2*s0v.x;  d[nt+2][0] = t2*c0.x + t1*s0v.x;
        t1 = d[nt][1]; t2 = d[nt+2][1];
        d[nt][1] = t1*c0.y - t2*s0v.y;  d[nt+2][1] = t2*c0.y + t1*s0v.y;
        t1 = d[nt][2]; t2 = d[nt+2][2];
        d[nt][2] = t1*c1.x - t2*s1v.x;  d[nt+2][2] = t2*c1.x + t1*s1v.x;
        t1 = d[nt][3]; t2 = d[nt+2][3];
        d[nt][3] = t1*c1.y - t2*s1v.y;  d[nt+2][3] = t2*c1.y + t1*s1v.y;
    }
    #pragma unroll
    for (int nt = 0; nt < 4; nt++){
        d[nt][0] = rtf(d[nt][0]); d[nt][1] = rtf(d[nt][1]);
        d[nt][2] = rtf(d[nt][2]); d[nt][3] = rtf(d[nt][3]);
    }
}

// ---- GEMM 16x32 tile with smem store. MODE 0 store/1 add/2 gelu; ROPE; ROUND; ZMASK ----
template<int IC, int OC, int SS, int DS, int MODE, int ROPE, int ROUND, int ZMASK>
__device__ __forceinline__ void mma_tile_p(const float* __restrict__ src,
        const float2* __restrict__ Wp, const float* __restrict__ bias,
        float* __restrict__ dst, int m0, int n0,
        const float* __restrict__ RCp, const float* __restrict__ RSp, int valid)
{
    const int lane = threadIdx.x & 31;
    const int g    = lane >> 2;
    const int tig  = lane & 3;
    const int NK   = IC / 8;

    float d[4][4];
    #pragma unroll
    for (int nt = 0; nt < 4; nt++){
        const float2 bb = *(const float2*)(bias + n0 + nt*8 + 2*tig);
        d[nt][0] = bb.x; d[nt][1] = bb.y; d[nt][2] = bb.x; d[nt][3] = bb.y;
    }
    const float* s0 = src + (m0 + g)*SS + tig;
    const float* s1 = src + (m0 + g + 8)*SS + tig;
    const float2* Wb = Wp + (size_t)(n0 + g)*4 + tig;

    float aC[4]; float2 bC[4];
    aC[0] = s0[0]; aC[1] = s1[0]; aC[2] = s0[4]; aC[3] = s1[4];
    #pragma unroll
    for (int nt = 0; nt < 4; nt++) bC[nt] = __ldg(Wb + nt*32);

    #pragma unroll 1
    for (int ks = 0; ks < NK; ks++){
        const int k1 = (ks + 1 < NK) ? (ks + 1)*8 : ks*8;
        const float2* Wn = Wb + (size_t)((ks + 1 < NK) ? (ks + 1) : ks)*OC*4;
        float aN[4]; float2 bN[4];
        aN[0] = s0[k1]; aN[1] = s1[k1]; aN[2] = s0[k1+4]; aN[3] = s1[k1+4];
        #pragma unroll
        for (int nt = 0; nt < 4; nt++) bN[nt] = __ldg(Wn + nt*32);
        uint32_t ua[4];
        #pragma unroll
        for (int i = 0; i < 4; i++) ua[i] = __float_as_uint(aC[i]);
        #pragma unroll
        for (int nt = 0; nt < 4; nt++){
            uint32_t ub[2] = { __float_as_uint(bC[nt].x), __float_as_uint(bC[nt].y) };
            mma_tf32(d[nt], ua, ub);
        }
        #pragma unroll
        for (int i = 0; i < 4; i++) aC[i] = aN[i];
        #pragma unroll
        for (int nt = 0; nt < 4; nt++) bC[nt] = bN[nt];
    }

    if (ROPE){
        #pragma unroll
        for (int nt = 0; nt < 2; nt++){
            const int j = nt*8 + 2*tig;
            const float2 c0 = *(const float2*)(RCp + (m0 + g)*16 + j);
            const float2 s0v= *(const float2*)(RSp + (m0 + g)*16 + j);
            const float2 c1 = *(const float2*)(RCp + (m0 + g + 8)*16 + j);
            const float2 s1v= *(const float2*)(RSp + (m0 + g + 8)*16 + j);
            float t1, t2;
            t1 = d[nt][0]; t2 = d[nt+2][0];
            d[nt][0] = t1*c0.x - t2*s0v.x;  d[nt+2][0] = t2*c0.x + t1*s0v.x;
            t1 = d[nt][1]; t2 = d[nt+2][1];
            d[nt][1] = t1*c0.y - t2*s0v.y;  d[nt+2][1] = t2*c0.y + t1*s0v.y;
            t1 = d[nt][2]; t2 = d[nt+2][2];
            d[nt][2] = t1*c1.x - t2*s1v.x;  d[nt+2][2] = t2*c1.x + t1*s1v.x;
            t1 = d[nt][3]; t2 = d[nt+2][3];
            d[nt][3] = t1*c1.y - t2*s1v.y;  d[nt+2][3] = t2*c1.y + t1*s1v.y;
        }
    }

    const bool z0 = ZMASK && (m0 + g     >= valid);
    const bool z1 = ZMASK && (m0 + g + 8 >= valid);
    #pragma unroll
    for (int nt = 0; nt < 4; nt++){
        const int c  = n0 + nt*8 + 2*tig;
        float* p0 = dst + (m0 + g)*DS + c;
        float* p1 = dst + (m0 + g + 8)*DS + c;
        if (MODE == 0){
            float v00, v01, v10, v11;
            if (ROUND){ v00=rtf(d[nt][0]); v01=rtf(d[nt][1]); v10=rtf(d[nt][2]); v11=rtf(d[nt][3]); }
            else      { v00=d[nt][0]; v01=d[nt][1]; v10=d[nt][2]; v11=d[nt][3]; }
            if (z0){ v00 = 0.f; v01 = 0.f; }
            if (z1){ v10 = 0.f; v11 = 0.f; }
            *(float2*)p0 = make_float2(v00, v01);
            *(float2*)p1 = make_float2(v10, v11);
        } else if (MODE == 1){
            float2 x0 = *(float2*)p0, x1 = *(float2*)p1;
            x0.x += d[nt][0]; x0.y += d[nt][1]; *(float2*)p0 = x0;
            x1.x += d[nt][2]; x1.y += d[nt][3]; *(float2*)p1 = x1;
        } else {
            *(float2*)p0 = make_float2(rtf(gelu_tanh(d[nt][0])), rtf(gelu_tanh(d[nt][1])));
            *(float2*)p1 = make_float2(rtf(gelu_tanh(d[nt][2])), rtf(gelu_tanh(d[nt][3])));
        }
    }
}

#define SMEM_FLOATS (4*Sn*SX /*X,H,K,V*/ + Sn*SF /*FF*/ + 2*Sn*16 /*rope*/)
#define SMEM_BYTES  (SMEM_FLOATS*4)

__global__ void __launch_bounds__(NTHREADS, 1) rowinteraction_kernel(
    const float* __restrict__ emb,  const float* __restrict__ cls,
    const float* __restrict__ ln1g, const float* __restrict__ ln1b,
    const float* __restrict__ bq,   const float* __restrict__ bk,
    const float* __restrict__ bv,   const float* __restrict__ bo,
    const float* __restrict__ ln2g, const float* __restrict__ ln2b,
    const float* __restrict__ b1,   const float* __restrict__ b2,
    const float* __restrict__ og,   const float* __restrict__ ob,
    const int*   __restrict__ dvec, float* __restrict__ out)
{
    extern __shared__ float smf[];
    float* X  = smf;                 // [64][132] residual (fp32)
    float* H  = X  + Sn*SX;          // [64][132] ln/attn out (tf32-rounded)
    float* Kb = H  + Sn*SX;
    float* Vb = Kb + Sn*SX;
    float* FF = Vb + Sn*SX;          // [64][260] separate (no overlay -> no cross-group race)
    float* RC = FF + Sn*SF;          // rope cos [64][16]
    float* RS = RC + Sn*16;

    const int tid   = threadIdx.x;
    const int warp  = tid >> 5;
    const int lane  = tid & 31;
    const int g     = lane >> 2;
    const int tig   = lane & 3;
    const int n     = blockIdx.x;
    const int bidx  = n >> 10;        // T = 1024
    const int valid = dvec[bidx] + Cn;          // 4..63
    const float scale = 0.17677669529663687f;   // 1/sqrt(32)

    const int mtw  = warp >> 2;       // this warp's m-tile (row group)
    const int ncw  = warp & 3;        // this warp's n-chunk / head
    const int m0w  = mtw*16;
    const int barid= mtw + 1;         // named barrier per row group (0 is syncthreads)

    for (int idx = tid; idx < Sn*16; idx += NTHREADS){
        int pos = idx >> 4, f = idx & 15;
        float inv = expf(-((float)(2*f) / (float)DHn) * logf(100000.0f));
        float ang = (float)pos * inv;
        RC[idx] = cosf(ang); RS[idx] = sinf(ang);
    }
    for (int idx = tid; idx < Sn*En; idx += NTHREADS){
        int r = idx >> 7, c = idx & 127;
        float v = (r < Cn) ? cls[r*En + c] : emb[((size_t)n*Sn + r)*En + c];
        X[r*SX + c] = v;
        if (r >= valid){ Kb[r*SX + c] = 0.f; Vb[r*SX + c] = 0.f; }  // dead K/V zero once
    }
    __syncthreads();

    const bool live = (m0w < valid);

    for (int l = 0; l < Ln; ++l){
        const float2* WL = g_wpacked + l*LSTRIDE;

        // LN1 (warp-local rows) -> QKV (warp-local tile; Q stays in registers)
        float qd[4][4];
        if (live){
            ln_warp(X, H, ln1g + l*En, ln1b + l*En, m0w, valid);
            __syncwarp();
            mma_tile_regs<En, En, SX>(H, WL, bq + l*En, m0w, ncw*32, RC, RS, qd);
            mma_tile_p<En, En, SX, SX, 0, 1, 1, 1>(H, WL + 8192,  bk + l*En, Kb,
                                                   m0w, ncw*32, RC, RS, valid);
            mma_tile_p<En, En, SX, SX, 0, 0, 1, 1>(H, WL + 16384, bv + l*En, Vb,
                                                   m0w, ncw*32, RC, RS, valid);
        }
        __syncthreads();   // FULL #1: K/V visible to all groups

        // ---- warp-local attention: head = ncw, m-tile = mtw; Q from registers ----
        if (live){
            const int qbase = ncw*DHn;    // == n0 of this warp's Q tile
            const int NKS = (valid + 7) >> 3;
            float dS[8][4];
            #pragma unroll
            for (int nt = 0; nt < 8; nt++)
                dS[nt][0] = dS[nt][1] = dS[nt][2] = dS[nt][3] = 0.f;
            const int srcl = g*4 + (tig >> 1);
            const bool hi  = (tig & 1);
            #pragma unroll
            for (int ks = 0; ks < 4; ks++){
                // A-frag for k-block ks from Q C-frags via in-warp shuffle
                float v0, v1;
                v0 = __shfl_sync(0xffffffffu, qd[ks][0], srcl);
                v1 = __shfl_sync(0xffffffffu, qd[ks][1], srcl);
                const float a0 = hi ? v1 : v0;
                v0 = __shfl_sync(0xffffffffu, qd[ks][2], srcl);
                v1 = __shfl_sync(0xffffffffu, qd[ks][3], srcl);
                const float a1 = hi ? v1 : v0;
                v0 = __shfl_sync(0xffffffffu, qd[ks][0], srcl + 2);
                v1 = __shfl_sync(0xffffffffu, qd[ks][1], srcl + 2);
                const float a2 = hi ? v1 : v0;
                v0 = __shfl_sync(0xffffffffu, qd[ks][2], srcl + 2);
                v1 = __shfl_sync(0xffffffffu, qd[ks][3], srcl + 2);
                const float a3 = hi ? v1 : v0;
                uint32_t ua[4] = { __float_as_uint(a0), __float_as_uint(a1),
                                   __float_as_uint(a2), __float_as_uint(a3) };
                const int k0 = ks*8;
                #pragma unroll
                for (int nt = 0; nt < 8; nt++){
                    if (nt < NKS){
                        const float* kp = Kb + (nt*8 + g)*SX + qbase + k0;
                        uint32_t ub[2] = { __float_as_uint(kp[tig]),
                                           __float_as_uint(kp[tig+4]) };
                        mma_tf32(dS[nt], ua, ub);
                    }
                }
            }
            // in-register softmax
            float mx0 = -1e30f, mx1 = -1e30f;
            #pragma unroll
            for (int nt = 0; nt < 8; nt++){
                #pragma unroll
                for (int c2 = 0; c2 < 2; c2++){
                    if (nt*8 + 2*tig + c2 < valid){
                        mx0 = fmaxf(mx0, dS[nt][c2]);
                        mx1 = fmaxf(mx1, dS[nt][2+c2]);
                    }
                }
            }
            mx0 = fmaxf(mx0, __shfl_xor_sync(0xffffffffu, mx0, 1));
            mx0 = fmaxf(mx0, __shfl_xor_sync(0xffffffffu, mx0, 2));
            mx1 = fmaxf(mx1, __shfl_xor_sync(0xffffffffu, mx1, 1));
            mx1 = fmaxf(mx1, __shfl_xor_sync(0xffffffffu, mx1, 2));
            mx0 *= scale; mx1 *= scale;
            float sm0 = 0.f, sm1 = 0.f;
            #pragma unroll
            for (int nt = 0; nt < 8; nt++){
                #pragma unroll
                for (int c2 = 0; c2 < 2; c2++){
                    const bool lv = (nt*8 + 2*tig + c2 < valid);
                    float e0 = lv ? __expf(dS[nt][c2]*scale   - mx0) : 0.f;
                    float e1 = lv ? __expf(dS[nt][2+c2]*scale - mx1) : 0.f;
                    dS[nt][c2]   = e0; sm0 += e0;
                    dS[nt][2+c2] = e1; sm1 += e1;
                }
            }
            sm0 += __shfl_xor_sync(0xffffffffu, sm0, 1);
            sm0 += __shfl_xor_sync(0xffffffffu, sm0, 2);
            sm1 += __shfl_xor_sync(0xffffffffu, sm1, 1);
            sm1 += __shfl_xor_sync(0xffffffffu, sm1, 2);
            const float iv0 = 1.0f / sm0, iv1 = 1.0f / sm1;
            #pragma unroll
            for (int nt = 0; nt < 8; nt++){
                dS[nt][0] = rtf(dS[nt][0]*iv0);
                dS[nt][1] = rtf(dS[nt][1]*iv0);
                dS[nt][2] = rtf(dS[nt][2]*iv1);
                dS[nt][3] = rtf(dS[nt][3]*iv1);
            }
            // PV via shuffled A-frags
            float dO[4][4];
            #pragma unroll
            for (int nt = 0; nt < 4; nt++)
                dO[nt][0] = dO[nt][1] = dO[nt][2] = dO[nt][3] = 0.f;
            #pragma unroll
            for (int ks = 0; ks < 8; ks++){
                if (ks < NKS){
                    float v0, v1;
                    v0 = __shfl_sync(0xffffffffu, dS[ks][0], srcl);
                    v1 = __shfl_sync(0xffffffffu, dS[ks][1], srcl);
                    const float a0 = hi ? v1 : v0;
                    v0 = __shfl_sync(0xffffffffu, dS[ks][2], srcl);
                    v1 = __shfl_sync(0xffffffffu, dS[ks][3], srcl);
                    const float a1 = hi ? v1 : v0;
                    v0 = __shfl_sync(0xffffffffu, dS[ks][0], srcl + 2);
                    v1 = __shfl_sync(0xffffffffu, dS[ks][1], srcl + 2);
                    const float a2 = hi ? v1 : v0;
                    v0 = __shfl_sync(0xffffffffu, dS[ks][2], srcl + 2);
                    v1 = __shfl_sync(0xffffffffu, dS[ks][3], srcl + 2);
                    const float a3 = hi ? v1 : v0;
                    uint32_t ua[4] = { __float_as_uint(a0), __float_as_uint(a1),
                                       __float_as_uint(a2), __float_as_uint(a3) };
                    const int k0 = ks*8;
                    #pragma unroll
                    for (int nt = 0; nt < 4; nt++){
                        const float* vp = Vb + (k0 + tig)*SX + qbase + nt*8 + g;
                        uint32_t ub[2] = { __float_as_uint(vp[0]),
                                           __float_as_uint(vp[4*SX]) };
                        mma_tf32(dO[nt], ua, ub);
                    }
                }
            }
            #pragma unroll
            for (int nt = 0; nt < 4; nt++){
                const int c = qbase + nt*8 + 2*tig;
                float* p = H + (m0w + g)*SX + c;
                *(float2*)p          = make_float2(rtf(dO[nt][0]), rtf(dO[nt][1]));
                *(float2*)(p + 8*SX) = make_float2(rtf(dO[nt][2]), rtf(dO[nt][3]));
            }
        }
        __syncthreads();   // FULL #2: all attention K/V reads done; H rows complete

        if (live){          // x += o @ wo + bo   (own rows)
            mma_tile_p<En, En, SX, SX, 1, 0, 0, 0>(H, WL + 24576, bo + l*En, X,
                                                   m0w, ncw*32, RC, RS, valid);
        }
        BAR_GROUP(barid);   // group: X rows complete for LN2

        if (live){
            ln_warp(X, H, ln2g + l*En, ln2b + l*En, m0w, valid);
            __syncwarp();
            mma_tile_p<En, FFn, SX, SF, 2, 0, 1, 0>(H, WL + 32768, b1 + l*FFn, FF,
                                                    m0w, ncw*32, RC, RS, valid);
            mma_tile_p<En, FFn, SX, SF, 2, 0, 1, 0>(H, WL + 32768, b1 + l*FFn, FF,
                                                    m0w, (ncw + 4)*32, RC, RS, valid);
        }
        BAR_GROUP(barid);   // group: FF rows complete for w2

        if (live){          // x += ff @ w2 + b2
            mma_tile_p<FFn, En, SF, SX, 1, 0, 0, 0>(FF, WL + 49152, b2 + l*En, X,
                                                    m0w, ncw*32, RC, RS, valid);
        }
        BAR_GROUP(barid);   // group: X rows complete for next LN1 / epilogue
    }

    // Epilogue: rows 0..3 belong to group 0 (warps 0..3) — already synced by its bar
    if (warp < Cn){
        const float4 xv = *(const float4*)(X + warp*SX + lane*4);
        float s  = xv.x + xv.y + xv.z + xv.w;
        float s2 = xv.x*xv.x + xv.y*xv.y + xv.z*xv.z + xv.w*xv.w;
        #pragma unroll
        for (int o = 16; o; o >>= 1){
            s  += __shfl_xor_sync(0xffffffffu, s,  o);
            s2 += __shfl_xor_sync(0xffffffffu, s2, o);
        }
        const float m    = s * 0.0078125f;
        const float rstd = rsqrtf(s2*0.0078125f - m*m + 1e-5f);
        const float4 gv  = *(const float4*)(og + lane*4);
        const float4 bv4 = *(const float4*)(ob + lane*4);
        float4 ovv;
        ovv.x = (xv.x - m)*rstd*gv.x + bv4.x;
        ovv.y = (xv.y - m)*rstd*gv.y + bv4.y;
        ovv.z = (xv.z - m)*rstd*gv.z + bv4.z;
        ovv.w = (xv.w - m)*rstd*gv.w + bv4.w;
        *(float4*)(out + (size_t)n*(Cn*En) + warp*En + lane*4) = ovv;
    }
}

extern "C" void kernel_launch(void* const* d_in, const int* in_sizes, int n_in,
                              void* d_out, int out_size)
{
    (void)in_sizes; (void)n_in; (void)out_size;
    prep_weights<<<dim3(32, 18), 256>>>(
        (const float*)d_in[4],  (const float*)d_in[6],  (const float*)d_in[8],
        (const float*)d_in[10], (const float*)d_in[14], (const float*)d_in[16]);
    cudaFuncSetAttribute(rowinteraction_kernel,
                         cudaFuncAttributeMaxDynamicSharedMemorySize, SMEM_BYTES);
    rowinteraction_kernel<<<Bn*Tn, NTHREADS, SMEM_BYTES>>>(
        (const float*)d_in[0],  (const float*)d_in[1],
        (const float*)d_in[2],  (const float*)d_in[3],
        (const float*)d_in[5],  (const float*)d_in[7],
        (const float*)d_in[9],  (const float*)d_in[11],
        (const float*)d_in[12], (const float*)d_in[13],
        (const float*)d_in[15], (const float*)d_in[17],
        (const float*)d_in[18], (const float*)d_in[19],
        (const int*)d_in[20],   (float*)d_out);
}